// round 6
// baseline (speedup 1.0000x reference)
#include <cuda_runtime.h>
#include <math.h>

#define B_   128
#define S_   512
#define IN_  128
#define H_   512
#define C_   1000
#define NBLK 128          // persistent grid: 8 x 16 blocks, 1 per SM
#define WSP  36           // Ws row pitch (floats), mult of 4, conflict-free
#define HSP  516          // Hs row pitch (floats), mult of 4, conflict-free

// Scratch (device globals: allocation-free per harness rules)
__device__ float g_xp [(size_t)B_ * S_ * H_];   // input projection (both layers)
__device__ float g_seq[(size_t)B_ * S_ * H_];   // layer-0 hidden sequence
__device__ float g_h  [2 * B_ * H_];            // double-buffered hidden state
__device__ unsigned g_arrive;                   // grid-barrier arrival counter
__device__ unsigned g_epoch;                    // grid-barrier epoch (monotonic)

// ---------------------------------------------------------------------------
// Software grid barrier. Safe across graph replays: epoch only grows, the
// arrival counter is reset by the last arriver before the epoch is released.
// Requires all NBLK blocks co-resident (NBLK <= #SMs, 1 block/SM).
// ---------------------------------------------------------------------------
__device__ __forceinline__ void grid_barrier(unsigned base, unsigned step) {
    __threadfence();          // publish this thread's global stores
    __syncthreads();          // whole block's stores fenced before arrival
    if (threadIdx.x == 0) {
        unsigned old = atomicAdd(&g_arrive, 1u);
        if (old == NBLK - 1) {
            g_arrive = 0;                 // no new arrivals until epoch bumps
            __threadfence();              // reset visible before release
            atomicAdd(&g_epoch, 1u);      // release
        } else {
            while ((*(volatile unsigned*)&g_epoch) - base < step)
                __nanosleep(32);
            __threadfence();              // acquire
        }
    }
    __syncthreads();
}

// ---------------------------------------------------------------------------
// Persistent RNN layer: 512 steps of Hn[128,512] = tanh(XP[:,t,:] + Hp@Whh^T)
// Grid (8,16) = 128 blocks, 256 threads. Block tile: 16 rows x 32 cols.
// Whh tile [32 x 512] lives in smem for the WHOLE layer. Per step, hp tile
// [16 x 512] is staged (L2-coherent __ldcg). 4 K-groups of 64 threads, each
// thread a 2x4 microtile over K=128 -> FFMA-bound inner loop.
// ---------------------------------------------------------------------------
__global__ void __launch_bounds__(256, 1) rnn_layer_kernel(
    const float* __restrict__ xp, const float* __restrict__ Wh,
    float* __restrict__ hA, float* __restrict__ hB,
    float* __restrict__ seqOut)
{
    extern __shared__ float sm[];
    float* Ws = sm;                    // [512][WSP]  (k-major, n contiguous)
    float* Hs = Ws + 512 * WSP;        // [16][HSP]   (m-major, k contiguous)
    float* Pr = Hs + 16 * HSP;         // [3][16][32] K-split partials
    __shared__ unsigned s_base;

    const int tid = threadIdx.x;
    const int m0  = blockIdx.x << 4;   // 8 blocks  -> 128 rows
    const int n0  = blockIdx.y << 5;   // 16 blocks -> 512 cols

    const int g   = tid >> 6;          // K group 0..3
    const int gt  = tid & 63;
    const int r0  = (gt >> 3) << 1;    // rows r0, r0+1 (0..14)
    const int c0  = (gt & 7) << 2;     // cols c0..c0+3 (0..28)

    if (tid == 0) s_base = *(volatile unsigned*)&g_epoch;  // stable pre-barrier

    // Load the block's Whh tile once: rows n0..n0+31, all K=512, as [k][n].
    for (int i = tid; i < 32 * 128; i += 256) {
        int n  = i >> 7;               // 0..31
        int k4 = i & 127;              // float4 index along K
        float4 v = *reinterpret_cast<const float4*>(
            &Wh[(size_t)(n0 + n) * H_ + (k4 << 2)]);
        int k = k4 << 2;
        Ws[(k + 0) * WSP + n] = v.x;
        Ws[(k + 1) * WSP + n] = v.y;
        Ws[(k + 2) * WSP + n] = v.z;
        Ws[(k + 3) * WSP + n] = v.w;
    }
    __syncthreads();

    for (int t = 0; t < S_; ++t) {
        const float* hp = (t & 1) ? hA : hB;
        float*       hn = (t & 1) ? hB : hA;

        float a00 = 0.f, a01 = 0.f, a02 = 0.f, a03 = 0.f;
        float a10 = 0.f, a11 = 0.f, a12 = 0.f, a13 = 0.f;

        if (t > 0) {
            // Stage hp tile [16 x 512] -> Hs (bypass L1: other blocks wrote it)
            for (int i = tid; i < 16 * 128; i += 256) {
                int r  = i >> 7;
                int k4 = i & 127;
                float4 v = __ldcg(reinterpret_cast<const float4*>(
                    &hp[(size_t)(m0 + r) * H_ + (k4 << 2)]));
                *reinterpret_cast<float4*>(&Hs[r * HSP + (k4 << 2)]) = v;
            }
            __syncthreads();

            const float* h0r = &Hs[r0 * HSP];
            const float* h1r = &Hs[(r0 + 1) * HSP];
            const int kbeg = g << 7;
#pragma unroll 8
            for (int k = kbeg; k < kbeg + 128; ++k) {
                float av0 = h0r[k];
                float av1 = h1r[k];
                float4 w = *reinterpret_cast<const float4*>(&Ws[k * WSP + c0]);
                a00 = fmaf(av0, w.x, a00); a01 = fmaf(av0, w.y, a01);
                a02 = fmaf(av0, w.z, a02); a03 = fmaf(av0, w.w, a03);
                a10 = fmaf(av1, w.x, a10); a11 = fmaf(av1, w.y, a11);
                a12 = fmaf(av1, w.z, a12); a13 = fmaf(av1, w.w, a13);
            }

            // K-split reduction: groups 1..3 dump partials, group 0 sums.
            if (g > 0) {
                float* p = &Pr[(((g - 1) << 4) + r0) * 32 + c0];
                *reinterpret_cast<float4*>(p)      = make_float4(a00, a01, a02, a03);
                *reinterpret_cast<float4*>(p + 32) = make_float4(a10, a11, a12, a13);
            }
            __syncthreads();
            if (g == 0) {
#pragma unroll
                for (int pg = 0; pg < 3; ++pg) {
                    const float* p = &Pr[((pg << 4) + r0) * 32 + c0];
                    float4 q0 = *reinterpret_cast<const float4*>(p);
                    float4 q1 = *reinterpret_cast<const float4*>(p + 32);
                    a00 += q0.x; a01 += q0.y; a02 += q0.z; a03 += q0.w;
                    a10 += q1.x; a11 += q1.y; a12 += q1.z; a13 += q1.w;
                }
            }
        }
        // t == 0: acc stays 0 (h_{-1} = 0), so output = tanh(xp).

        if (g == 0) {
            int m = m0 + r0;
            int n = n0 + c0;
            size_t xi0 = ((size_t)m * S_ + t) * H_ + n;
            size_t xi1 = xi0 + (size_t)S_ * H_;
            float4 x0 = *reinterpret_cast<const float4*>(&xp[xi0]);
            float4 x1 = *reinterpret_cast<const float4*>(&xp[xi1]);
            float4 o0, o1;
            o0.x = tanhf(a00 + x0.x); o0.y = tanhf(a01 + x0.y);
            o0.z = tanhf(a02 + x0.z); o0.w = tanhf(a03 + x0.w);
            o1.x = tanhf(a10 + x1.x); o1.y = tanhf(a11 + x1.y);
            o1.z = tanhf(a12 + x1.z); o1.w = tanhf(a13 + x1.w);
            __stcg(reinterpret_cast<float4*>(&hn[(size_t)m * H_ + n]), o0);
            __stcg(reinterpret_cast<float4*>(&hn[(size_t)(m + 1) * H_ + n]), o1);
            if (seqOut) {
                __stcg(reinterpret_cast<float4*>(&seqOut[xi0]), o0);
                __stcg(reinterpret_cast<float4*>(&seqOut[xi1]), o1);
            }
        }

        if (t != S_ - 1) grid_barrier(s_base, (unsigned)(t + 1));
    }
}

// ---------------------------------------------------------------------------
// C[M,N] = A[M,K] @ W[N,K]^T + b1[N] + b2[N]
// 64x64 tile, BK=16, 256 threads, 4x4 microtile. M%64==0, N%64==0, K%16==0.
// ---------------------------------------------------------------------------
__global__ __launch_bounds__(256) void sgemm_bias(
    const float* __restrict__ A, const float* __restrict__ W,
    const float* __restrict__ b1, const float* __restrict__ b2,
    float* __restrict__ C, int M, int N, int K)
{
    __shared__ float As[16][64];
    __shared__ float Wt[16][64];
    int tid = threadIdx.x;
    int tx = tid & 15, ty = tid >> 4;
    int m0 = blockIdx.x * 64, n0 = blockIdx.y * 64;
    int lr = tid >> 2;
    int lk = (tid & 3) << 2;
    const float* Aptr = A + (size_t)(m0 + lr) * K + lk;
    const float* Wptr = W + (size_t)(n0 + lr) * K + lk;
    float acc[4][4] = {};

    for (int k0 = 0; k0 < K; k0 += 16) {
        float4 av = *(const float4*)(Aptr + k0);
        float4 wv = *(const float4*)(Wptr + k0);
        As[lk + 0][lr] = av.x; As[lk + 1][lr] = av.y;
        As[lk + 2][lr] = av.z; As[lk + 3][lr] = av.w;
        Wt[lk + 0][lr] = wv.x; Wt[lk + 1][lr] = wv.y;
        Wt[lk + 2][lr] = wv.z; Wt[lk + 3][lr] = wv.w;
        __syncthreads();
#pragma unroll
        for (int kk = 0; kk < 16; kk++) {
            float4 a = *(const float4*)&As[kk][ty << 2];
            float4 w = *(const float4*)&Wt[kk][tx << 2];
            acc[0][0] += a.x * w.x; acc[0][1] += a.x * w.y; acc[0][2] += a.x * w.z; acc[0][3] += a.x * w.w;
            acc[1][0] += a.y * w.x; acc[1][1] += a.y * w.y; acc[1][2] += a.y * w.z; acc[1][3] += a.y * w.w;
            acc[2][0] += a.z * w.x; acc[2][1] += a.z * w.y; acc[2][2] += a.z * w.z; acc[2][3] += a.z * w.w;
            acc[3][0] += a.w * w.x; acc[3][1] += a.w * w.y; acc[3][2] += a.w * w.z; acc[3][3] += a.w * w.w;
        }
        __syncthreads();
    }

    int n = n0 + (tx << 2);
    float bb0 = b1[n + 0] + b2[n + 0];
    float bb1 = b1[n + 1] + b2[n + 1];
    float bb2 = b1[n + 2] + b2[n + 2];
    float bb3 = b1[n + 3] + b2[n + 3];
#pragma unroll
    for (int i = 0; i < 4; i++) {
        int m = m0 + (ty << 2) + i;
        float4 o;
        o.x = acc[i][0] + bb0; o.y = acc[i][1] + bb1;
        o.z = acc[i][2] + bb2; o.w = acc[i][3] + bb3;
        *(float4*)&C[(size_t)m * N + n] = o;
    }
}

// ---------------------------------------------------------------------------
// logits = h_last @ W_out^T + b_out; out = log_softmax(logits)
// ---------------------------------------------------------------------------
__global__ __launch_bounds__(256) void out_kernel(
    const float* __restrict__ h, const float* __restrict__ Wout,
    const float* __restrict__ bout, float* __restrict__ out)
{
    __shared__ float hs[H_];
    __shared__ float logits[C_];
    __shared__ float red[8];
    int b = blockIdx.x;
    int tid = threadIdx.x;
    int warp = tid >> 5, lane = tid & 31;

    for (int k = tid; k < H_; k += 256) hs[k] = h[(size_t)b * H_ + k];
    __syncthreads();

    for (int c = warp; c < C_; c += 8) {
        const float* wr = Wout + (size_t)c * H_;
        float s = 0.f;
#pragma unroll
        for (int k = lane; k < H_; k += 32) s += hs[k] * wr[k];
#pragma unroll
        for (int off = 16; off > 0; off >>= 1) s += __shfl_down_sync(0xffffffffu, s, off);
        if (lane == 0) logits[c] = s + bout[c];
    }
    __syncthreads();

    float mx = -1e30f;
    for (int c = tid; c < C_; c += 256) mx = fmaxf(mx, logits[c]);
#pragma unroll
    for (int off = 16; off > 0; off >>= 1) mx = fmaxf(mx, __shfl_down_sync(0xffffffffu, mx, off));
    if (lane == 0) red[warp] = mx;
    __syncthreads();
    if (tid == 0) {
        float m2 = red[0];
        for (int i = 1; i < 8; i++) m2 = fmaxf(m2, red[i]);
        red[0] = m2;
    }
    __syncthreads();
    mx = red[0];
    __syncthreads();

    float se = 0.f;
    for (int c = tid; c < C_; c += 256) se += expf(logits[c] - mx);
#pragma unroll
    for (int off = 16; off > 0; off >>= 1) se += __shfl_down_sync(0xffffffffu, se, off);
    if (lane == 0) red[warp] = se;
    __syncthreads();
    if (tid == 0) {
        float s2 = 0.f;
        for (int i = 0; i < 8; i++) s2 += red[i];
        red[0] = logf(s2);
    }
    __syncthreads();
    float lse = red[0];

    for (int c = tid; c < C_; c += 256)
        out[(size_t)b * C_ + c] = logits[c] - mx - lse;
}

extern "C" void kernel_launch(void* const* d_in, const int* in_sizes, int n_in,
                              void* d_out, int out_size)
{
    (void)in_sizes; (void)n_in; (void)out_size;
    const float* x     = (const float*)d_in[0];
    const float* W_ih0 = (const float*)d_in[1];
    const float* W_hh0 = (const float*)d_in[2];
    const float* b_ih0 = (const float*)d_in[3];
    const float* b_hh0 = (const float*)d_in[4];
    const float* W_ih1 = (const float*)d_in[5];
    const float* W_hh1 = (const float*)d_in[6];
    const float* b_ih1 = (const float*)d_in[7];
    const float* b_hh1 = (const float*)d_in[8];
    const float* W_out = (const float*)d_in[9];
    const float* b_out = (const float*)d_in[10];
    float* out = (float*)d_out;

    float *xp, *seq, *hbuf;
    cudaGetSymbolAddress((void**)&xp,   g_xp);
    cudaGetSymbolAddress((void**)&seq,  g_seq);
    cudaGetSymbolAddress((void**)&hbuf, g_h);
    float* hA = hbuf;
    float* hB = hbuf + B_ * H_;

    const int smem_bytes = (512 * WSP + 16 * HSP + 3 * 16 * 32) * 4;  // 112896
    cudaFuncSetAttribute(rnn_layer_kernel,
                         cudaFuncAttributeMaxDynamicSharedMemorySize, smem_bytes);

    dim3 gg(B_ * S_ / 64, H_ / 64);   // (1024, 8)
    dim3 gr(B_ / 16, H_ / 32);        // (8, 16) = 128 persistent blocks

    // layer 0: input projection, then persistent recurrence (writes g_seq)
    sgemm_bias<<<gg, 256>>>(x, W_ih0, b_ih0, b_hh0, xp, B_ * S_, H_, IN_);
    rnn_layer_kernel<<<gr, 256, smem_bytes>>>(xp, W_hh0, hA, hB, seq);

    // layer 1: input projection on g_seq, then persistent recurrence
    sgemm_bias<<<gg, 256>>>(seq, W_ih1, b_ih1, b_hh1, xp, B_ * S_, H_, H_);
    rnn_layer_kernel<<<gr, 256, smem_bytes>>>(xp, W_hh1, hA, hB, nullptr);

    // output head on h_{S-1} (t=511 is odd -> final state in hB)
    out_kernel<<<B_, 256>>>(hB, W_out, b_out, out);
}

// round 7
// speedup vs baseline: 1.3684x; 1.3684x over previous
#include <cuda_runtime.h>
#include <math.h>

#define B_   128
#define S_   512
#define IN_  128
#define H_   512
#define C_   1000
#define NBLK 128          // persistent grid: 8 x 16 blocks, 1 per SM
#define HSP  516          // Hs row pitch (floats): 516*4 % 16 == 0

// Scratch (device globals: allocation-free per harness rules)
__device__ float g_xp [(size_t)B_ * S_ * H_];   // input projection (both layers)
__device__ float g_seq[(size_t)B_ * S_ * H_];   // layer-0 hidden sequence
__device__ float g_h  [2 * B_ * H_];            // double-buffered hidden state
__device__ unsigned g_arrive;                   // grid-barrier arrival counter
__device__ unsigned g_epoch;                    // grid-barrier epoch (monotonic)

// ---------------------------------------------------------------------------
// Software grid barrier (monotonic epoch; replay-safe). All NBLK blocks
// co-resident (1 block/SM, NBLK <= #SMs).
// ---------------------------------------------------------------------------
__device__ __forceinline__ void grid_barrier(unsigned base, unsigned step) {
    __threadfence();
    __syncthreads();
    if (threadIdx.x == 0) {
        unsigned old = atomicAdd(&g_arrive, 1u);
        if (old == NBLK - 1) {
            g_arrive = 0;
            __threadfence();
            atomicAdd(&g_epoch, 1u);
        } else {
            while ((*(volatile unsigned*)&g_epoch) - base < step)
                __nanosleep(20);
            __threadfence();
        }
    }
    __syncthreads();
}

// ---------------------------------------------------------------------------
// Persistent RNN layer: 512 steps of Hn[128,512] = tanh(XP[:,t,:] + Hp@Whh^T)
// Grid (8,16) = 128 blocks, 256 threads (8 warps). Block tile 16 rows x 32 cols.
// Whh tile [K=512][32] stays in smem all layer. One warp = one K-group of 64.
// Thread microtile 4 rows x 4 cols, k-vectorized by 4 (float4 on h and w).
// 8-way partials reduced in parallel by all 256 threads (2 outputs each).
// ---------------------------------------------------------------------------
__global__ void __launch_bounds__(256, 1) rnn_layer_kernel(
    const float* __restrict__ xp, const float* __restrict__ Wh,
    float* __restrict__ hA, float* __restrict__ hB,
    float* __restrict__ seqOut)
{
    extern __shared__ float sm[];
    float* Ws = sm;                    // [512][32] k-major, n contiguous (64KB)
    float* Hs = Ws + 512 * 32;         // [16][HSP] m-major, k contiguous (33KB)
    float* Pr = Hs + 16 * HSP;         // [8][16][32] per-warp partials (16KB)
    __shared__ unsigned s_base;

    const int tid = threadIdx.x;
    const int m0  = blockIdx.x << 4;   // 8 m-tiles  -> 128 rows
    const int n0  = blockIdx.y << 5;   // 16 n-tiles -> 512 cols

    const int g    = tid >> 5;             // warp = K-group 0..7
    const int lane = tid & 31;
    const int r0   = (lane >> 3) << 2;     // rows r0..r0+3 (0,4,8,12)
    const int c0   = (lane & 7) << 2;      // cols c0..c0+3 (0..28)

    if (tid == 0) s_base = *(volatile unsigned*)&g_epoch;

    // Load Whh tile once: Ws[k][n] for n in [n0,n0+32), k in [0,512).
    // Global reads uncoalesced (one-time); smem stores conflict-free.
    for (int i = tid; i < 32 * 128; i += 256) {
        int n  = i & 31;
        int k4 = i >> 5;               // 0..127
        float4 v = *reinterpret_cast<const float4*>(
            &Wh[(size_t)(n0 + n) * H_ + (k4 << 2)]);
        int k = k4 << 2;
        Ws[(k + 0) * 32 + n] = v.x;
        Ws[(k + 1) * 32 + n] = v.y;
        Ws[(k + 2) * 32 + n] = v.z;
        Ws[(k + 3) * 32 + n] = v.w;
    }
    __syncthreads();

    // Epilogue output indices for this thread (2 outputs, coalesced)
    const int i0 = tid, i1 = tid + 256;
    const int er0 = i0 >> 5, ec0 = i0 & 31;
    const int er1 = i1 >> 5, ec1 = i1 & 31;

    for (int t = 0; t < S_; ++t) {
        const float* hp = (t & 1) ? hA : hB;
        float*       hn = (t & 1) ? hB : hA;

        // Prefetch xp for this step (consumed in epilogue, hidden under MMA)
        size_t xbase0 = ((size_t)(m0 + er0) * S_ + t) * H_ + n0 + ec0;
        size_t xbase1 = ((size_t)(m0 + er1) * S_ + t) * H_ + n0 + ec1;
        float xv0 = __ldg(&xp[xbase0]);
        float xv1 = __ldg(&xp[xbase1]);

        float s0 = 0.f, s1 = 0.f;

        if (t > 0) {
            // Stage hp tile [16 x 512] -> Hs (L2-coherent)
            for (int j = 0; j < 8; ++j) {
                int i  = tid + (j << 8);
                int r  = i >> 7;
                int k4 = i & 127;
                float4 v = __ldcg(reinterpret_cast<const float4*>(
                    &hp[(size_t)(m0 + r) * H_ + (k4 << 2)]));
                *reinterpret_cast<float4*>(&Hs[r * HSP + (k4 << 2)]) = v;
            }
            __syncthreads();

            float acc[4][4];
#pragma unroll
            for (int a = 0; a < 4; ++a)
#pragma unroll
                for (int b = 0; b < 4; ++b) acc[a][b] = 0.f;

            const int kbeg = g << 6;      // 64 k per warp
#pragma unroll 4
            for (int k4i = 0; k4i < 16; ++k4i) {
                int k = kbeg + (k4i << 2);
                float4 h0 = *reinterpret_cast<const float4*>(&Hs[(r0 + 0) * HSP + k]);
                float4 h1 = *reinterpret_cast<const float4*>(&Hs[(r0 + 1) * HSP + k]);
                float4 h2 = *reinterpret_cast<const float4*>(&Hs[(r0 + 2) * HSP + k]);
                float4 h3 = *reinterpret_cast<const float4*>(&Hs[(r0 + 3) * HSP + k]);
                float4 w0 = *reinterpret_cast<const float4*>(&Ws[(k + 0) * 32 + c0]);
                float4 w1 = *reinterpret_cast<const float4*>(&Ws[(k + 1) * 32 + c0]);
                float4 w2 = *reinterpret_cast<const float4*>(&Ws[(k + 2) * 32 + c0]);
                float4 w3 = *reinterpret_cast<const float4*>(&Ws[(k + 3) * 32 + c0]);
#define RNN_FMA_ROW(i, hv)                                                    \
                acc[i][0] = fmaf(hv.x, w0.x, acc[i][0]);                      \
                acc[i][1] = fmaf(hv.x, w0.y, acc[i][1]);                      \
                acc[i][2] = fmaf(hv.x, w0.z, acc[i][2]);                      \
                acc[i][3] = fmaf(hv.x, w0.w, acc[i][3]);                      \
                acc[i][0] = fmaf(hv.y, w1.x, acc[i][0]);                      \
                acc[i][1] = fmaf(hv.y, w1.y, acc[i][1]);                      \
                acc[i][2] = fmaf(hv.y, w1.z, acc[i][2]);                      \
                acc[i][3] = fmaf(hv.y, w1.w, acc[i][3]);                      \
                acc[i][0] = fmaf(hv.z, w2.x, acc[i][0]);                      \
                acc[i][1] = fmaf(hv.z, w2.y, acc[i][1]);                      \
                acc[i][2] = fmaf(hv.z, w2.z, acc[i][2]);                      \
                acc[i][3] = fmaf(hv.z, w2.w, acc[i][3]);                      \
                acc[i][0] = fmaf(hv.w, w3.x, acc[i][0]);                      \
                acc[i][1] = fmaf(hv.w, w3.y, acc[i][1]);                      \
                acc[i][2] = fmaf(hv.w, w3.z, acc[i][2]);                      \
                acc[i][3] = fmaf(hv.w, w3.w, acc[i][3]);
                RNN_FMA_ROW(0, h0)
                RNN_FMA_ROW(1, h1)
                RNN_FMA_ROW(2, h2)
                RNN_FMA_ROW(3, h3)
#undef RNN_FMA_ROW
            }

            // Write per-warp partials: Pr[g][r][c]
            float* pg = &Pr[(g << 9)];
#pragma unroll
            for (int a = 0; a < 4; ++a) {
                *reinterpret_cast<float4*>(&pg[(r0 + a) * 32 + c0]) =
                    make_float4(acc[a][0], acc[a][1], acc[a][2], acc[a][3]);
            }
            __syncthreads();

            // Parallel 8-way reduction (2 outputs/thread, conflict-free)
#pragma unroll
            for (int gg = 0; gg < 8; ++gg) {
                s0 += Pr[(gg << 9) + i0];
                s1 += Pr[(gg << 9) + i1];
            }
            __syncthreads();   // Pr reusable next step
        }

        // Epilogue: tanh + store (coalesced scalar stores)
        float v0 = tanhf(s0 + xv0);
        float v1 = tanhf(s1 + xv1);
        __stcg(&hn[(size_t)(m0 + er0) * H_ + n0 + ec0], v0);
        __stcg(&hn[(size_t)(m0 + er1) * H_ + n0 + ec1], v1);
        if (seqOut) {
            __stcg(&seqOut[xbase0], v0);
            __stcg(&seqOut[xbase1], v1);
        }

        if (t != S_ - 1) grid_barrier(s_base, (unsigned)(t + 1));
    }
}

// ---------------------------------------------------------------------------
// C[M,N] = A[M,K] @ W[N,K]^T + b1[N] + b2[N]
// 128x64 tile, BK=16, 256 threads, 8x4 microtile. M%128==0, N%64==0, K%16==0.
// ---------------------------------------------------------------------------
__global__ __launch_bounds__(256) void sgemm_bias(
    const float* __restrict__ A, const float* __restrict__ W,
    const float* __restrict__ b1, const float* __restrict__ b2,
    float* __restrict__ C, int M, int N, int K)
{
    __shared__ float As[16][132];
    __shared__ float Wt[16][68];
    const int tid = threadIdx.x;
    const int tx = tid & 15, ty = tid >> 4;
    const int m0 = blockIdx.x * 128, n0 = blockIdx.y * 64;

    float acc[8][4];
#pragma unroll
    for (int i = 0; i < 8; ++i)
#pragma unroll
        for (int j = 0; j < 4; ++j) acc[i][j] = 0.f;

    for (int k0 = 0; k0 < K; k0 += 16) {
        // A tile 128x16 -> As[k][m] (512 float4, 2/thread)
#pragma unroll
        for (int j = 0; j < 2; ++j) {
            int i  = tid + (j << 8);
            int lr = i >> 2;
            int lk = (i & 3) << 2;
            float4 v = *reinterpret_cast<const float4*>(&A[(size_t)(m0 + lr) * K + k0 + lk]);
            As[lk + 0][lr] = v.x; As[lk + 1][lr] = v.y;
            As[lk + 2][lr] = v.z; As[lk + 3][lr] = v.w;
        }
        // W tile 64x16 -> Wt[k][n] (256 float4, 1/thread)
        {
            int ln = tid >> 2;
            int lk = (tid & 3) << 2;
            float4 v = *reinterpret_cast<const float4*>(&W[(size_t)(n0 + ln) * K + k0 + lk]);
            Wt[lk + 0][ln] = v.x; Wt[lk + 1][ln] = v.y;
            Wt[lk + 2][ln] = v.z; Wt[lk + 3][ln] = v.w;
        }
        __syncthreads();
#pragma unroll
        for (int kk = 0; kk < 16; ++kk) {
            float4 a0 = *reinterpret_cast<const float4*>(&As[kk][ty << 3]);
            float4 a1 = *reinterpret_cast<const float4*>(&As[kk][(ty << 3) + 4]);
            float4 w  = *reinterpret_cast<const float4*>(&Wt[kk][tx << 2]);
            acc[0][0] += a0.x * w.x; acc[0][1] += a0.x * w.y; acc[0][2] += a0.x * w.z; acc[0][3] += a0.x * w.w;
            acc[1][0] += a0.y * w.x; acc[1][1] += a0.y * w.y; acc[1][2] += a0.y * w.z; acc[1][3] += a0.y * w.w;
            acc[2][0] += a0.z * w.x; acc[2][1] += a0.z * w.y; acc[2][2] += a0.z * w.z; acc[2][3] += a0.z * w.w;
            acc[3][0] += a0.w * w.x; acc[3][1] += a0.w * w.y; acc[3][2] += a0.w * w.z; acc[3][3] += a0.w * w.w;
            acc[4][0] += a1.x * w.x; acc[4][1] += a1.x * w.y; acc[4][2] += a1.x * w.z; acc[4][3] += a1.x * w.w;
            acc[5][0] += a1.y * w.x; acc[5][1] += a1.y * w.y; acc[5][2] += a1.y * w.z; acc[5][3] += a1.y * w.w;
            acc[6][0] += a1.z * w.x; acc[6][1] += a1.z * w.y; acc[6][2] += a1.z * w.z; acc[6][3] += a1.z * w.w;
            acc[7][0] += a1.w * w.x; acc[7][1] += a1.w * w.y; acc[7][2] += a1.w * w.z; acc[7][3] += a1.w * w.w;
        }
        __syncthreads();
    }

    const int n = n0 + (tx << 2);
    float bb0 = b1[n + 0] + b2[n + 0];
    float bb1 = b1[n + 1] + b2[n + 1];
    float bb2 = b1[n + 2] + b2[n + 2];
    float bb3 = b1[n + 3] + b2[n + 3];
#pragma unroll
    for (int i = 0; i < 8; ++i) {
        int m = m0 + (ty << 3) + i;
        float4 o;
        o.x = acc[i][0] + bb0; o.y = acc[i][1] + bb1;
        o.z = acc[i][2] + bb2; o.w = acc[i][3] + bb3;
        *reinterpret_cast<float4*>(&C[(size_t)m * N + n]) = o;
    }
}

// ---------------------------------------------------------------------------
// logits = h_last @ W_out^T + b_out; out = log_softmax(logits)
// ---------------------------------------------------------------------------
__global__ __launch_bounds__(256) void out_kernel(
    const float* __restrict__ h, const float* __restrict__ Wout,
    const float* __restrict__ bout, float* __restrict__ out)
{
    __shared__ float hs[H_];
    __shared__ float logits[C_];
    __shared__ float red[8];
    int b = blockIdx.x;
    int tid = threadIdx.x;
    int warp = tid >> 5, lane = tid & 31;

    for (int k = tid; k < H_; k += 256) hs[k] = h[(size_t)b * H_ + k];
    __syncthreads();

    for (int c = warp; c < C_; c += 8) {
        const float* wr = Wout + (size_t)c * H_;
        float s = 0.f;
#pragma unroll
        for (int k = lane; k < H_; k += 32) s += hs[k] * wr[k];
#pragma unroll
        for (int off = 16; off > 0; off >>= 1) s += __shfl_down_sync(0xffffffffu, s, off);
        if (lane == 0) logits[c] = s + bout[c];
    }
    __syncthreads();

    float mx = -1e30f;
    for (int c = tid; c < C_; c += 256) mx = fmaxf(mx, logits[c]);
#pragma unroll
    for (int off = 16; off > 0; off >>= 1) mx = fmaxf(mx, __shfl_down_sync(0xffffffffu, mx, off));
    if (lane == 0) red[warp] = mx;
    __syncthreads();
    if (tid == 0) {
        float m2 = red[0];
        for (int i = 1; i < 8; i++) m2 = fmaxf(m2, red[i]);
        red[0] = m2;
    }
    __syncthreads();
    mx = red[0];
    __syncthreads();

    float se = 0.f;
    for (int c = tid; c < C_; c += 256) se += expf(logits[c] - mx);
#pragma unroll
    for (int off = 16; off > 0; off >>= 1) se += __shfl_down_sync(0xffffffffu, se, off);
    if (lane == 0) red[warp] = se;
    __syncthreads();
    if (tid == 0) {
        float s2 = 0.f;
        for (int i = 0; i < 8; i++) s2 += red[i];
        red[0] = logf(s2);
    }
    __syncthreads();
    float lse = red[0];

    for (int c = tid; c < C_; c += 256)
        out[(size_t)b * C_ + c] = logits[c] - mx - lse;
}

extern "C" void kernel_launch(void* const* d_in, const int* in_sizes, int n_in,
                              void* d_out, int out_size)
{
    (void)in_sizes; (void)n_in; (void)out_size;
    const float* x     = (const float*)d_in[0];
    const float* W_ih0 = (const float*)d_in[1];
    const float* W_hh0 = (const float*)d_in[2];
    const float* b_ih0 = (const float*)d_in[3];
    const float* b_hh0 = (const float*)d_in[4];
    const float* W_ih1 = (const float*)d_in[5];
    const float* W_hh1 = (const float*)d_in[6];
    const float* b_ih1 = (const float*)d_in[7];
    const float* b_hh1 = (const float*)d_in[8];
    const float* W_out = (const float*)d_in[9];
    const float* b_out = (const float*)d_in[10];
    float* out = (float*)d_out;

    float *xp, *seq, *hbuf;
    cudaGetSymbolAddress((void**)&xp,   g_xp);
    cudaGetSymbolAddress((void**)&seq,  g_seq);
    cudaGetSymbolAddress((void**)&hbuf, g_h);
    float* hA = hbuf;
    float* hB = hbuf + B_ * H_;

    const int smem_bytes = (512 * 32 + 16 * HSP + 8 * 512) * 4;  // 114944
    cudaFuncSetAttribute(rnn_layer_kernel,
                         cudaFuncAttributeMaxDynamicSharedMemorySize, smem_bytes);

    dim3 gg(B_ * S_ / 128, H_ / 64);  // (512, 8)
    dim3 gr(B_ / 16, H_ / 32);        // (8, 16) = 128 persistent blocks

    // layer 0
    sgemm_bias<<<gg, 256>>>(x, W_ih0, b_ih0, b_hh0, xp, B_ * S_, H_, IN_);
    rnn_layer_kernel<<<gr, 256, smem_bytes>>>(xp, W_hh0, hA, hB, seq);

    // layer 1
    sgemm_bias<<<gg, 256>>>(seq, W_ih1, b_ih1, b_hh1, xp, B_ * S_, H_, H_);
    rnn_layer_kernel<<<gr, 256, smem_bytes>>>(xp, W_hh1, hA, hB, nullptr);

    // output head on h_{S-1} (t=511 odd -> final state in hB)
    out_kernel<<<B_, 256>>>(hB, W_out, b_out, out);
}

// round 8
// speedup vs baseline: 1.4351x; 1.0488x over previous
#include <cuda_runtime.h>
#include <math.h>

#define B_   128
#define S_   512
#define IN_  128
#define H_   512
#define C_   1000
#define NBLK 128          // persistent grid: 8 x 16 blocks, 1 per SM
#define HP   68           // per-warp Hs row pitch (floats), 16B-aligned

// Scratch (device globals: allocation-free per harness rules)
__device__ float g_xp [(size_t)B_ * S_ * H_];   // input projection (both layers)
__device__ float g_seq[(size_t)B_ * S_ * H_];   // layer-0 hidden sequence
__device__ float g_h  [2 * B_ * H_];            // double-buffered hidden state
__device__ unsigned g_arr2[8];                  // per-m-group arrival counters
__device__ unsigned g_ep2[8];                   // per-m-group epochs (monotonic)

// ---------------- packed fp32x2 helpers (SASS FFMA2 path) -------------------
__device__ __forceinline__ unsigned long long pack2(float lo, float hi) {
    unsigned long long d;
    asm("mov.b64 %0, {%1, %2};" : "=l"(d)
        : "r"(__float_as_uint(lo)), "r"(__float_as_uint(hi)));
    return d;
}
__device__ __forceinline__ unsigned long long ffma2(
    unsigned long long a, unsigned long long b, unsigned long long c) {
    unsigned long long d;
    asm("fma.rn.f32x2 %0, %1, %2, %3;" : "=l"(d) : "l"(a), "l"(b), "l"(c));
    return d;
}
__device__ __forceinline__ unsigned long long fadd2(
    unsigned long long a, unsigned long long b) {
    unsigned long long d;
    asm("add.rn.f32x2 %0, %1, %2;" : "=l"(d) : "l"(a), "l"(b));
    return d;
}
__device__ __forceinline__ float2 unpack2(unsigned long long v) {
    unsigned lo, hi;
    asm("mov.b64 {%0, %1}, %2;" : "=r"(lo), "=r"(hi) : "l"(v));
    return make_float2(__uint_as_float(lo), __uint_as_float(hi));
}

// ---------------------------------------------------------------------------
// 16-block group barrier (blocks sharing blockIdx.x). Monotonic epoch,
// replay-safe. All blocks co-resident (1/SM).
// ---------------------------------------------------------------------------
__device__ __forceinline__ void barrier16(int grp, unsigned base, unsigned step) {
    __threadfence();
    __syncthreads();
    if (threadIdx.x == 0) {
        unsigned old = atomicAdd(&g_arr2[grp], 1u);
        if (old == 15u) {
            g_arr2[grp] = 0;
            __threadfence();
            atomicAdd(&g_ep2[grp], 1u);
        } else {
            while ((*(volatile unsigned*)&g_ep2[grp]) - base < step) { }
            __threadfence();
        }
    }
    __syncthreads();
}

// ---------------------------------------------------------------------------
// Persistent RNN layer: 512 steps of Hn[128,512] = tanh(XP[:,t,:] + Hp@Whh^T)
// Grid (8,16) = 128 blocks, 256 threads (8 warps). Block tile 16 rows x 32 cols.
// Whh tile [512][32] resident in smem all layer. Warp g owns k-slice
// [64g, 64g+64): stages its own 16x64 Hs region (syncwarp only), computes a
// 4x4 microtile per thread with packed f32x2 FMAs, dumps packed partials,
// block-reduces 8-way, tanh-stores.
// ---------------------------------------------------------------------------
__global__ void __launch_bounds__(256, 1) rnn_layer_kernel(
    const float* __restrict__ xp, const float* __restrict__ Wh,
    float* __restrict__ hA, float* __restrict__ hB,
    float* __restrict__ seqOut)
{
    extern __shared__ float sm[];
    float* Ws = sm;                     // [512][32] k-major        (64 KB)
    float* Hs = Ws + 512 * 32;          // 8 x [16][HP] per-warp    (34 KB)
    float* Pr = Hs + 8 * 16 * HP;       // [8][512] packed partials (16 KB)
    __shared__ unsigned s_base;

    const int tid  = threadIdx.x;
    const int bx   = blockIdx.x;
    const int m0   = bx << 4;            // 8 m-groups  -> 128 rows
    const int n0   = blockIdx.y << 5;    // 16 n-groups -> 512 cols
    const int g    = tid >> 5;           // warp = K-group 0..7
    const int lane = tid & 31;
    const int r0   = (lane >> 3) << 2;   // rows r0..r0+3
    const int c0   = (lane & 7) << 2;    // cols c0..c0+3
    float* HsW = Hs + g * (16 * HP);

    if (tid == 0) s_base = *(volatile unsigned*)&g_ep2[bx];

    // Load Whh tile once: Ws[k][n], n in [n0, n0+32), k in [0,512)
    for (int i = tid; i < 32 * 128; i += 256) {
        int n  = i & 31;
        int k4 = i >> 5;
        float4 v = *reinterpret_cast<const float4*>(
            &Wh[(size_t)(n0 + n) * H_ + (k4 << 2)]);
        int k = k4 << 2;
        Ws[(k + 0) * 32 + n] = v.x;
        Ws[(k + 1) * 32 + n] = v.y;
        Ws[(k + 2) * 32 + n] = v.z;
        Ws[(k + 3) * 32 + n] = v.w;
    }
    __syncthreads();

    // Epilogue: thread owns 2 adjacent outputs (one f32x2)
    const int i0 = tid << 1;
    const int er = tid >> 4;             // 0..15
    const int ec = i0 & 31;              // even 0..30
    const int kbeg = g << 6;

    for (int t = 0; t < S_; ++t) {
        const float* hp = (t & 1) ? hA : hB;
        float*       hn = (t & 1) ? hB : hA;

        size_t xi = ((size_t)(m0 + er) * S_ + t) * H_ + n0 + ec;
        float2 xv = __ldg(reinterpret_cast<const float2*>(&xp[xi]));

        float s0 = 0.f, s1 = 0.f;

        if (t > 0) {
            // Per-warp staging of own k-slice (16 rows x 64 k)
#pragma unroll
            for (int j = 0; j < 8; ++j) {
                int idx = lane + (j << 5);
                int r = idx >> 4, k4 = idx & 15;
                float4 v = __ldcg(reinterpret_cast<const float4*>(
                    &hp[(size_t)(m0 + r) * H_ + kbeg + (k4 << 2)]));
                *reinterpret_cast<float4*>(&HsW[r * HP + (k4 << 2)]) = v;
            }
            __syncwarp();

            unsigned long long a00 = 0, a01 = 0, a10 = 0, a11 = 0;
            unsigned long long a20 = 0, a21 = 0, a30 = 0, a31 = 0;

#pragma unroll 4
            for (int k4i = 0; k4i < 16; ++k4i) {
                const int kk = k4i << 2;
                float4 h0 = *reinterpret_cast<const float4*>(&HsW[(r0 + 0) * HP + kk]);
                float4 h1 = *reinterpret_cast<const float4*>(&HsW[(r0 + 1) * HP + kk]);
                float4 h2 = *reinterpret_cast<const float4*>(&HsW[(r0 + 2) * HP + kk]);
                float4 h3 = *reinterpret_cast<const float4*>(&HsW[(r0 + 3) * HP + kk]);
#define RNN_SUBK(s, C)                                                         \
                {                                                              \
                    const ulonglong2 w = *reinterpret_cast<const ulonglong2*>( \
                        &Ws[(kbeg + kk + s) * 32 + c0]);                       \
                    unsigned long long d;                                      \
                    d = pack2(h0.C, h0.C);                                     \
                    a00 = ffma2(d, w.x, a00); a01 = ffma2(d, w.y, a01);        \
                    d = pack2(h1.C, h1.C);                                     \
                    a10 = ffma2(d, w.x, a10); a11 = ffma2(d, w.y, a11);        \
                    d = pack2(h2.C, h2.C);                                     \
                    a20 = ffma2(d, w.x, a20); a21 = ffma2(d, w.y, a21);        \
                    d = pack2(h3.C, h3.C);                                     \
                    a30 = ffma2(d, w.x, a30); a31 = ffma2(d, w.y, a31);        \
                }
                RNN_SUBK(0, x)
                RNN_SUBK(1, y)
                RNN_SUBK(2, z)
                RNN_SUBK(3, w)
#undef RNN_SUBK
            }

            // Packed partials: Pr[g][row][col-pair] (bit-identical to floats)
            float* pg = &Pr[g << 9];
            *reinterpret_cast<ulonglong2*>(&pg[(r0 + 0) * 32 + c0]) = make_ulonglong2(a00, a01);
            *reinterpret_cast<ulonglong2*>(&pg[(r0 + 1) * 32 + c0]) = make_ulonglong2(a10, a11);
            *reinterpret_cast<ulonglong2*>(&pg[(r0 + 2) * 32 + c0]) = make_ulonglong2(a20, a21);
            *reinterpret_cast<ulonglong2*>(&pg[(r0 + 3) * 32 + c0]) = make_ulonglong2(a30, a31);
            __syncthreads();

            unsigned long long sp = 0;
#pragma unroll
            for (int gg = 0; gg < 8; ++gg)
                sp = fadd2(sp, *reinterpret_cast<const unsigned long long*>(
                                   &Pr[(gg << 9) + i0]));
            float2 sf = unpack2(sp);
            s0 = sf.x; s1 = sf.y;
        }
        // t == 0: h_{-1}=0 -> output = tanh(xp)

        float2 o;
        o.x = tanhf(s0 + xv.x);
        o.y = tanhf(s1 + xv.y);
        __stcg(reinterpret_cast<float2*>(&hn[(size_t)(m0 + er) * H_ + n0 + ec]), o);
        if (seqOut)
            __stcg(reinterpret_cast<float2*>(&seqOut[xi]), o);

        if (t != S_ - 1) barrier16(bx, s_base, (unsigned)(t + 1));
    }
}

// ---------------------------------------------------------------------------
// C[M,N] = A[M,K] @ W[N,K]^T + b1[N] + b2[N]
// 128x64 tile, BK=16, 256 threads, 8x4 microtile, packed f32x2 FMAs.
// ---------------------------------------------------------------------------
__global__ __launch_bounds__(256) void sgemm_bias(
    const float* __restrict__ A, const float* __restrict__ W,
    const float* __restrict__ b1, const float* __restrict__ b2,
    float* __restrict__ C, int M, int N, int K)
{
    __shared__ float As[16][132];
    __shared__ float Wt[16][68];
    const int tid = threadIdx.x;
    const int tx = tid & 15, ty = tid >> 4;
    const int m0 = blockIdx.x * 128, n0 = blockIdx.y * 64;

    unsigned long long acc[8][2];
#pragma unroll
    for (int i = 0; i < 8; ++i) { acc[i][0] = 0; acc[i][1] = 0; }

    for (int k0 = 0; k0 < K; k0 += 16) {
#pragma unroll
        for (int j = 0; j < 2; ++j) {
            int i  = tid + (j << 8);
            int lr = i >> 2;
            int lk = (i & 3) << 2;
            float4 v = *reinterpret_cast<const float4*>(&A[(size_t)(m0 + lr) * K + k0 + lk]);
            As[lk + 0][lr] = v.x; As[lk + 1][lr] = v.y;
            As[lk + 2][lr] = v.z; As[lk + 3][lr] = v.w;
        }
        {
            int ln = tid >> 2;
            int lk = (tid & 3) << 2;
            float4 v = *reinterpret_cast<const float4*>(&W[(size_t)(n0 + ln) * K + k0 + lk]);
            Wt[lk + 0][ln] = v.x; Wt[lk + 1][ln] = v.y;
            Wt[lk + 2][ln] = v.z; Wt[lk + 3][ln] = v.w;
        }
        __syncthreads();
#pragma unroll
        for (int kk = 0; kk < 16; ++kk) {
            float4 x0 = *reinterpret_cast<const float4*>(&As[kk][ty << 3]);
            float4 x1 = *reinterpret_cast<const float4*>(&As[kk][(ty << 3) + 4]);
            const ulonglong2 w = *reinterpret_cast<const ulonglong2*>(&Wt[kk][tx << 2]);
            unsigned long long d;
#define GEMM_ROW(i, av, C)                                                     \
            d = pack2(av.C, av.C);                                             \
            acc[i][0] = ffma2(d, w.x, acc[i][0]);                              \
            acc[i][1] = ffma2(d, w.y, acc[i][1]);
            GEMM_ROW(0, x0, x) GEMM_ROW(1, x0, y) GEMM_ROW(2, x0, z) GEMM_ROW(3, x0, w)
            GEMM_ROW(4, x1, x) GEMM_ROW(5, x1, y) GEMM_ROW(6, x1, z) GEMM_ROW(7, x1, w)
#undef GEMM_ROW
        }
        __syncthreads();
    }

    const int n = n0 + (tx << 2);
    unsigned long long bb0 = pack2(b1[n + 0] + b2[n + 0], b1[n + 1] + b2[n + 1]);
    unsigned long long bb1 = pack2(b1[n + 2] + b2[n + 2], b1[n + 3] + b2[n + 3]);
#pragma unroll
    for (int i = 0; i < 8; ++i) {
        int m = m0 + (ty << 3) + i;
        *reinterpret_cast<ulonglong2*>(&C[(size_t)m * N + n]) =
            make_ulonglong2(fadd2(acc[i][0], bb0), fadd2(acc[i][1], bb1));
    }
}

// ---------------------------------------------------------------------------
// logits = h_last @ W_out^T + b_out; out = log_softmax(logits)
// ---------------------------------------------------------------------------
__global__ __launch_bounds__(256) void out_kernel(
    const float* __restrict__ h, const float* __restrict__ Wout,
    const float* __restrict__ bout, float* __restrict__ out)
{
    __shared__ float hs[H_];
    __shared__ float logits[C_];
    __shared__ float red[8];
    int b = blockIdx.x;
    int tid = threadIdx.x;
    int warp = tid >> 5, lane = tid & 31;

    for (int k = tid; k < H_; k += 256) hs[k] = h[(size_t)b * H_ + k];
    __syncthreads();

    for (int c = warp; c < C_; c += 8) {
        const float* wr = Wout + (size_t)c * H_;
        float s = 0.f;
#pragma unroll
        for (int k = lane; k < H_; k += 32) s += hs[k] * wr[k];
#pragma unroll
        for (int off = 16; off > 0; off >>= 1) s += __shfl_down_sync(0xffffffffu, s, off);
        if (lane == 0) logits[c] = s + bout[c];
    }
    __syncthreads();

    float mx = -1e30f;
    for (int c = tid; c < C_; c += 256) mx = fmaxf(mx, logits[c]);
#pragma unroll
    for (int off = 16; off > 0; off >>= 1) mx = fmaxf(mx, __shfl_down_sync(0xffffffffu, mx, off));
    if (lane == 0) red[warp] = mx;
    __syncthreads();
    if (tid == 0) {
        float m2 = red[0];
        for (int i = 1; i < 8; i++) m2 = fmaxf(m2, red[i]);
        red[0] = m2;
    }
    __syncthreads();
    mx = red[0];
    __syncthreads();

    float se = 0.f;
    for (int c = tid; c < C_; c += 256) se += expf(logits[c] - mx);
#pragma unroll
    for (int off = 16; off > 0; off >>= 1) se += __shfl_down_sync(0xffffffffu, se, off);
    if (lane == 0) red[warp] = se;
    __syncthreads();
    if (tid == 0) {
        float s2 = 0.f;
        for (int i = 0; i < 8; i++) s2 += red[i];
        red[0] = logf(s2);
    }
    __syncthreads();
    float lse = red[0];

    for (int c = tid; c < C_; c += 256)
        out[(size_t)b * C_ + c] = logits[c] - mx - lse;
}

extern "C" void kernel_launch(void* const* d_in, const int* in_sizes, int n_in,
                              void* d_out, int out_size)
{
    (void)in_sizes; (void)n_in; (void)out_size;
    const float* x     = (const float*)d_in[0];
    const float* W_ih0 = (const float*)d_in[1];
    const float* W_hh0 = (const float*)d_in[2];
    const float* b_ih0 = (const float*)d_in[3];
    const float* b_hh0 = (const float*)d_in[4];
    const float* W_ih1 = (const float*)d_in[5];
    const float* W_hh1 = (const float*)d_in[6];
    const float* b_ih1 = (const float*)d_in[7];
    const float* b_hh1 = (const float*)d_in[8];
    const float* W_out = (const float*)d_in[9];
    const float* b_out = (const float*)d_in[10];
    float* out = (float*)d_out;

    float *xp, *seq, *hbuf;
    cudaGetSymbolAddress((void**)&xp,   g_xp);
    cudaGetSymbolAddress((void**)&seq,  g_seq);
    cudaGetSymbolAddress((void**)&hbuf, g_h);
    float* hA = hbuf;
    float* hB = hbuf + B_ * H_;

    const int smem_bytes = (512 * 32 + 8 * 16 * HP + 8 * 512) * 4;  // 116736
    cudaFuncSetAttribute(rnn_layer_kernel,
                         cudaFuncAttributeMaxDynamicSharedMemorySize, smem_bytes);

    dim3 gg(B_ * S_ / 128, H_ / 64);  // (512, 8)
    dim3 gr(B_ / 16, H_ / 32);        // (8, 16) = 128 persistent blocks

    // layer 0
    sgemm_bias<<<gg, 256>>>(x, W_ih0, b_ih0, b_hh0, xp, B_ * S_, H_, IN_);
    rnn_layer_kernel<<<gr, 256, smem_bytes>>>(xp, W_hh0, hA, hB, seq);

    // layer 1
    sgemm_bias<<<gg, 256>>>(seq, W_ih1, b_ih1, b_hh1, xp, B_ * S_, H_, H_);
    rnn_layer_kernel<<<gr, 256, smem_bytes>>>(xp, W_hh1, hA, hB, nullptr);

    // output head on h_{S-1} (t=511 odd -> final state in hB)
    out_kernel<<<B_, 256>>>(hB, W_out, b_out, out);
}